// round 11
// baseline (speedup 1.0000x reference)
#include <cuda_runtime.h>
#include <stdint.h>

// FloodPath: 16-step binary flood fill, bit-packed, L2-resident planes.
// R11: pack -> 4 launches of a 4-step-fused CA kernel (3-row halo pyramid,
// redundant compute) -> unpack with channel-aligned float4 stores.

#define HW    4096
#define WPR   128                 // 32-bit words per row
#define NWORD (HW * WPR)          // 524288 words = 2 MB per plane
#define STEPS 16

__device__ uint32_t g_free[NWORD];              // bit=1: cell is free
__device__ uint32_t g_plane[STEPS + 1][NWORD];  // flood after step t

// ---- pack: warp ballots 32 cells -> 1 word. Coalesced 256B loads.
__global__ void __launch_bounds__(256)
pack_kernel(const float2* __restrict__ in)
{
    const int warp = (blockIdx.x * 256 + threadIdx.x) >> 5;
    const int lane = threadIdx.x & 31;
    const int w0   = warp * 32;
#pragma unroll 4
    for (int i = 0; i < 32; i++) {
        int w = w0 + i;
        float2 v = in[(size_t)w * 32 + lane];
        uint32_t fr = __ballot_sync(0xffffffffu, v.x == 0.f);
        uint32_t fl = __ballot_sync(0xffffffffu, v.y != 0.f);
        if (lane == 0) { g_free[w] = fr; g_plane[0][w] = fl; }
    }
}

// one CA step for a uint4 row segment (lane = 4 words of a 4096-bit row)
__device__ __forceinline__ uint4
castep(const uint4 up, const uint4 s, const uint4 dn, const uint4 fr, int lane)
{
    uint32_t lf = __shfl_up_sync(0xffffffffu, s.w, 1);
    uint32_t rt = __shfl_down_sync(0xffffffffu, s.x, 1);
    if (lane == 0)  lf = 0u;
    if (lane == 31) rt = 0u;
    uint4 o;
    o.x = (s.x | up.x | dn.x | __funnelshift_l(lf,  s.x, 1)
                             | __funnelshift_r(s.x, s.y, 1)) & fr.x;
    o.y = (s.y | up.y | dn.y | __funnelshift_l(s.x, s.y, 1)
                             | __funnelshift_r(s.y, s.z, 1)) & fr.y;
    o.z = (s.z | up.z | dn.z | __funnelshift_l(s.y, s.z, 1)
                             | __funnelshift_r(s.z, s.w, 1)) & fr.z;
    o.w = (s.w | up.w | dn.w | __funnelshift_l(s.z, s.w, 1)
                             | __funnelshift_r(s.w, rt,  1)) & fr.w;
    return o;
}

// ---- 4 fused steps: reads plane t-1, writes planes t..t+3 at row y.
// Pyramid: A on rows y-3..y+3, B on y-2..y+2, C on y-1..y+1, D on y.
__global__ void __launch_bounds__(512)
fstep4_kernel(int t)
{
    const uint32_t* __restrict__ src = g_plane[t - 1];

    const int g    = blockIdx.x * 512 + threadIdx.x;  // uint4 group id
    const int y    = g >> 5;                          // row
    const int lane = threadIdx.x & 31;
    const int b    = g * 4;

    const uint4 z = make_uint4(0u, 0u, 0u, 0u);

    uint4 s[9];   // flood rows y-4 .. y+4
    uint4 f[7];   // free  rows y-3 .. y+3
#pragma unroll
    for (int i = 0; i < 9; i++) {
        int r = y + i - 4;
        s[i] = ((unsigned)r < HW) ? *(const uint4*)(src + b + (i - 4) * WPR) : z;
    }
#pragma unroll
    for (int i = 0; i < 7; i++) {
        int r = y + i - 3;
        f[i] = ((unsigned)r < HW) ? *(const uint4*)(g_free + b + (i - 3) * WPR) : z;
    }

    uint4 a[7];   // step A: rows y-3 .. y+3
#pragma unroll
    for (int i = 0; i < 7; i++)
        a[i] = castep(s[i], s[i + 1], s[i + 2], f[i], lane);
    *(uint4*)(g_plane[t] + b) = a[3];

    uint4 bb[5];  // step B: rows y-2 .. y+2
#pragma unroll
    for (int i = 0; i < 5; i++)
        bb[i] = castep(a[i], a[i + 1], a[i + 2], f[i + 1], lane);
    *(uint4*)(g_plane[t + 1] + b) = bb[2];

    uint4 c[3];   // step C: rows y-1 .. y+1
#pragma unroll
    for (int i = 0; i < 3; i++)
        c[i] = castep(bb[i], bb[i + 1], bb[i + 2], f[i + 2], lane);
    *(uint4*)(g_plane[t + 2] + b) = c[1];

    // step D: row y
    const uint4 d = castep(c[0], c[1], c[2], f[3], lane);
    *(uint4*)(g_plane[t + 3] + b) = d;
}

// ---- unpack: lane owns word w0+lane (coalesced loads, 16-plane count
// ripple). Then 8 groups of 4 words: lane handles cells lane*4..lane*4+3
// (channel-aligned -> exactly 3 float4 stores per lane per group).
__global__ void __launch_bounds__(256)
unpack_kernel(float* __restrict__ out)
{
    const int w    = blockIdx.x * 256 + threadIdx.x;
    const int lane = threadIdx.x & 31;
    const int w0   = w - lane;

    const uint32_t fr = g_free[w];
    const uint32_t fw = g_plane[STEPS][w];

    uint32_t c0 = 0u, c1 = 0u, c2 = 0u, c3 = 0u, c4 = 0u;
#pragma unroll
    for (int t = 1; t <= STEPS; t++) {
        uint32_t carry = g_plane[t][w], x;
        x = c0 & carry; c0 ^= carry; carry = x;
        x = c1 & carry; c1 ^= carry; carry = x;
        x = c2 & carry; c2 ^= carry; carry = x;
        x = c3 & carry; c3 ^= carry; carry = x;
        c4 ^= carry;
    }

#pragma unroll
    for (int k = 0; k < 8; k++) {
        const int sl = k * 4 + (lane >> 3);     // source lane = word of group
        const uint32_t bfr = __shfl_sync(0xffffffffu, fr, sl);
        const uint32_t bfw = __shfl_sync(0xffffffffu, fw, sl);
        const uint32_t b0  = __shfl_sync(0xffffffffu, c0, sl);
        const uint32_t b1  = __shfl_sync(0xffffffffu, c1, sl);
        const uint32_t b2  = __shfl_sync(0xffffffffu, c2, sl);
        const uint32_t b3  = __shfl_sync(0xffffffffu, c3, sl);
        const uint32_t b4  = __shfl_sync(0xffffffffu, c4, sl);

        float v[12];
#pragma unroll
        for (int j = 0; j < 4; j++) {
            const int bit = (lane & 7) * 4 + j;
            const uint32_t cc =  ((b0 >> bit) & 1u)
                              | (((b1 >> bit) & 1u) << 1)
                              | (((b2 >> bit) & 1u) << 2)
                              | (((b3 >> bit) & 1u) << 3)
                              | (((b4 >> bit) & 1u) << 4);
            v[j * 3 + 0] = (float)(((bfr >> bit) & 1u) ^ 1u);  // occupied
            v[j * 3 + 1] = (float)((bfw >> bit) & 1u);         // flood
            v[j * 3 + 2] = (float)cc;                          // count
        }

        float4* o = (float4*)(out + (size_t)(w0 + k * 4) * 96 + lane * 12);
        o[0] = make_float4(v[0], v[1], v[2],  v[3]);
        o[1] = make_float4(v[4], v[5], v[6],  v[7]);
        o[2] = make_float4(v[8], v[9], v[10], v[11]);
    }
}

extern "C" void kernel_launch(void* const* d_in, const int* in_sizes, int n_in,
                              void* d_out, int out_size)
{
    const float2* in  = (const float2*)d_in[0];  // flood_input [H,W,2] f32
    float*        out = (float*)d_out;           // [H,W,3] f32
    (void)in_sizes; (void)n_in; (void)out_size;

    pack_kernel<<<2048, 256>>>(in);
    for (int t = 1; t <= STEPS; t += 4)
        fstep4_kernel<<<256, 512>>>(t);          // 4 steps per launch
    unpack_kernel<<<2048, 256>>>(out);
}

// round 12
// speedup vs baseline: 1.2416x; 1.2416x over previous
#include <cuda_runtime.h>
#include <stdint.h>

// FloodPath: 16-step binary flood fill, bit-packed, L2-resident planes.
// R12: pack -> 8 launches of fstep2 (proven R10) -> unpack with output-major
// shfl redistribution: every store is a fully coalesced STG.128 (min L1
// wavefronts); source words fetched via per-lane-indexed shfl (off L1 port).

#define HW    4096
#define WPR   128                 // 32-bit words per row
#define NWORD (HW * WPR)          // 524288 words = 2 MB per plane
#define STEPS 16

__device__ uint32_t g_free[NWORD];              // bit=1: cell is free
__device__ uint32_t g_plane[STEPS + 1][NWORD];  // flood after step t

// ---- pack: warp ballots 32 cells -> 1 word. Coalesced 256B loads.
__global__ void __launch_bounds__(256)
pack_kernel(const float2* __restrict__ in)
{
    const int warp = (blockIdx.x * 256 + threadIdx.x) >> 5;
    const int lane = threadIdx.x & 31;
    const int w0   = warp * 32;
#pragma unroll 4
    for (int i = 0; i < 32; i++) {
        int w = w0 + i;
        float2 v = in[(size_t)w * 32 + lane];
        uint32_t fr = __ballot_sync(0xffffffffu, v.x == 0.f);
        uint32_t fl = __ballot_sync(0xffffffffu, v.y != 0.f);
        if (lane == 0) { g_free[w] = fr; g_plane[0][w] = fl; }
    }
}

// one CA step for a uint4 row segment (lane = 4 words of a 4096-bit row)
__device__ __forceinline__ uint4
castep(const uint4 up, const uint4 s, const uint4 dn, const uint4 fr, int lane)
{
    uint32_t lf = __shfl_up_sync(0xffffffffu, s.w, 1);
    uint32_t rt = __shfl_down_sync(0xffffffffu, s.x, 1);
    if (lane == 0)  lf = 0u;
    if (lane == 31) rt = 0u;
    uint4 o;
    o.x = (s.x | up.x | dn.x | __funnelshift_l(lf,  s.x, 1)
                             | __funnelshift_r(s.x, s.y, 1)) & fr.x;
    o.y = (s.y | up.y | dn.y | __funnelshift_l(s.x, s.y, 1)
                             | __funnelshift_r(s.y, s.z, 1)) & fr.y;
    o.z = (s.z | up.z | dn.z | __funnelshift_l(s.y, s.z, 1)
                             | __funnelshift_r(s.z, s.w, 1)) & fr.z;
    o.w = (s.w | up.w | dn.w | __funnelshift_l(s.z, s.w, 1)
                             | __funnelshift_r(s.w, rt,  1)) & fr.w;
    return o;
}

// ---- 2 fused steps (proven R10): reads plane t-1, writes planes t, t+1.
__global__ void __launch_bounds__(512)
fstep_kernel(int t)
{
    const uint32_t* __restrict__ src = g_plane[t - 1];
    uint32_t*       __restrict__ dA  = g_plane[t];
    uint32_t*       __restrict__ dB  = g_plane[t + 1];

    const int g    = blockIdx.x * 512 + threadIdx.x;  // uint4 group id
    const int y    = g >> 5;                          // row
    const int lane = threadIdx.x & 31;
    const int b    = g * 4;

    const uint4 z = make_uint4(0u, 0u, 0u, 0u);
    const uint4 sm2 = (y > 1)      ? *(const uint4*)(src + b - 2 * WPR) : z;
    const uint4 sm1 = (y > 0)      ? *(const uint4*)(src + b - WPR)     : z;
    const uint4 s0  =                *(const uint4*)(src + b);
    const uint4 sp1 = (y < HW - 1) ? *(const uint4*)(src + b + WPR)     : z;
    const uint4 sp2 = (y < HW - 2) ? *(const uint4*)(src + b + 2 * WPR) : z;
    const uint4 fm1 = (y > 0)      ? *(const uint4*)(g_free + b - WPR)  : z;
    const uint4 f0  =                *(const uint4*)(g_free + b);
    const uint4 fp1 = (y < HW - 1) ? *(const uint4*)(g_free + b + WPR)  : z;

    const uint4 a_m1 = castep(sm2, sm1, s0,  fm1, lane);
    const uint4 a_0  = castep(sm1, s0,  sp1, f0,  lane);
    const uint4 a_p1 = castep(s0,  sp1, sp2, fp1, lane);
    *(uint4*)(dA + b) = a_0;

    const uint4 b_0 = castep(a_m1, a_0, a_p1, f0, lane);
    *(uint4*)(dB + b) = b_0;
}

// decode one cell's (occ, fld, cnt) floats from 7 source words
__device__ __forceinline__ void
decode_cell(uint32_t bfr, uint32_t bfw, uint32_t b0, uint32_t b1, uint32_t b2,
            uint32_t b3, uint32_t b4, int bit, float& occ, float& fld, float& cnt)
{
    occ = (float)(((bfr >> bit) & 1u) ^ 1u);
    fld = (float)((bfw >> bit) & 1u);
    uint32_t c =  ((b0 >> bit) & 1u)
               | (((b1 >> bit) & 1u) << 1)
               | (((b2 >> bit) & 1u) << 2)
               | (((b3 >> bit) & 1u) << 3)
               | (((b4 >> bit) & 1u) << 4);
    cnt = (float)c;
}

// ---- unpack, output-major: warp covers 32 words -> 768 output float4.
// float4 #j lies entirely in source word j/24 (96 floats per word = 24
// float4). Lane fetches its source word via indexed shfl and emits one
// fully coalesced STG.128 per iteration (4 wavefronts per 512B = minimum).
__global__ void __launch_bounds__(256)
unpack_kernel(float* __restrict__ out)
{
    const int w    = blockIdx.x * 256 + threadIdx.x;  // this lane's word
    const int lane = threadIdx.x & 31;
    const int w0   = w - lane;                        // warp's first word

    const uint32_t fr = g_free[w];
    const uint32_t fw = g_plane[STEPS][w];

    uint32_t c0 = 0u, c1 = 0u, c2 = 0u, c3 = 0u, c4 = 0u;
#pragma unroll
    for (int t = 1; t <= STEPS; t++) {
        uint32_t carry = g_plane[t][w], x;
        x = c0 & carry; c0 ^= carry; carry = x;
        x = c1 & carry; c1 ^= carry; carry = x;
        x = c2 & carry; c2 ^= carry; carry = x;
        x = c3 & carry; c3 ^= carry; carry = x;
        c4 ^= carry;
    }

    float4* out4 = (float4*)out + (size_t)w0 * 24;    // warp's output base

#pragma unroll
    for (int i = 0; i < 24; i++) {
        const int j  = i * 32 + lane;                 // output float4 index
        const int sw = j / 24;                        // source lane (word)
        const int jj = j - sw * 24;                   // float4 within word
        const int q4 = jj * 4;
        const int cb = q4 / 3;                        // first cell bit
        const int p  = q4 - cb * 3;                   // channel phase 0/1/2

        const uint32_t bfr = __shfl_sync(0xffffffffu, fr, sw);
        const uint32_t bfw = __shfl_sync(0xffffffffu, fw, sw);
        const uint32_t b0  = __shfl_sync(0xffffffffu, c0, sw);
        const uint32_t b1  = __shfl_sync(0xffffffffu, c1, sw);
        const uint32_t b2  = __shfl_sync(0xffffffffu, c2, sw);
        const uint32_t b3  = __shfl_sync(0xffffffffu, c3, sw);
        const uint32_t b4  = __shfl_sync(0xffffffffu, c4, sw);

        float o0, f0, n0, o1, f1, n1;
        decode_cell(bfr, bfw, b0, b1, b2, b3, b4, cb,     o0, f0, n0);
        decode_cell(bfr, bfw, b0, b1, b2, b3, b4, cb + 1, o1, f1, n1);

        float4 v;
        v.x = (p == 0) ? o0 : ((p == 1) ? f0 : n0);
        v.y = (p == 0) ? f0 : ((p == 1) ? n0 : o1);
        v.z = (p == 0) ? n0 : ((p == 1) ? o1 : f1);
        v.w = (p == 0) ? o1 : ((p == 1) ? f1 : n1);

        out4[j] = v;                                  // coalesced 512B/warp
    }
}

extern "C" void kernel_launch(void* const* d_in, const int* in_sizes, int n_in,
                              void* d_out, int out_size)
{
    const float2* in  = (const float2*)d_in[0];  // flood_input [H,W,2] f32
    float*        out = (float*)d_out;           // [H,W,3] f32
    (void)in_sizes; (void)n_in; (void)out_size;

    pack_kernel<<<2048, 256>>>(in);
    for (int t = 1; t <= STEPS; t += 2)
        fstep_kernel<<<256, 512>>>(t);           // 2 steps per launch
    unpack_kernel<<<2048, 256>>>(out);
}